// round 1
// baseline (speedup 1.0000x reference)
#include <cuda_runtime.h>
#include <cuda_bf16.h>
#include <math.h>

// Problem constants
#define BQ 2
#define SQ 2048
#define DM 1024
#define NH 16
#define DK 64
#define MROWS (BQ*SQ)   // 4096

// ---------------- scratch (allocation-free rule: __device__ globals) ----------------
__device__ float g_q[MROWS * DM];
__device__ float g_k[MROWS * DM];
__device__ float g_v[MROWS * DM];
__device__ float g_ctx[MROWS * DM];

// ---------------- GEMM: C[m,n] = sum_k A[m,k]*W[n,k] + bias[n] ----------------
// A: [M,K] row-major, W: [N,K] row-major (torch Linear => x @ W^T + b)
#define BM 64
#define BN 64
#define BK 16

__global__ void __launch_bounds__(256) gemm_nt_bias(
    const float* __restrict__ A,
    const float* __restrict__ W,
    const float* __restrict__ bias,
    float* __restrict__ C,
    int M, int N, int K)
{
    __shared__ float As[BK][BM + 4];
    __shared__ float Ws[BK][BN + 4];

    int tid = threadIdx.x;
    int tx = tid & 15;         // 0..15
    int ty = tid >> 4;         // 0..15
    int m0 = blockIdx.y * BM;
    int n0 = blockIdx.x * BN;

    int lr  = tid >> 2;        // 0..63  (row within tile)
    int lk4 = (tid & 3) * 4;   // k offset within BK (float4)

    float acc[4][4] = {};

    for (int k0 = 0; k0 < K; k0 += BK) {
        float4 av = *(const float4*)(A + (size_t)(m0 + lr) * K + k0 + lk4);
        float4 wv = *(const float4*)(W + (size_t)(n0 + lr) * K + k0 + lk4);
        As[lk4 + 0][lr] = av.x; As[lk4 + 1][lr] = av.y;
        As[lk4 + 2][lr] = av.z; As[lk4 + 3][lr] = av.w;
        Ws[lk4 + 0][lr] = wv.x; Ws[lk4 + 1][lr] = wv.y;
        Ws[lk4 + 2][lr] = wv.z; Ws[lk4 + 3][lr] = wv.w;
        __syncthreads();

        #pragma unroll
        for (int k = 0; k < BK; k++) {
            float4 a4 = *(const float4*)&As[k][ty * 4];
            float4 b4 = *(const float4*)&Ws[k][tx * 4];
            float a[4] = {a4.x, a4.y, a4.z, a4.w};
            float b[4] = {b4.x, b4.y, b4.z, b4.w};
            #pragma unroll
            for (int i = 0; i < 4; i++)
                #pragma unroll
                for (int j = 0; j < 4; j++)
                    acc[i][j] = fmaf(a[i], b[j], acc[i][j]);
        }
        __syncthreads();
    }

    #pragma unroll
    for (int i = 0; i < 4; i++) {
        int m = m0 + ty * 4 + i;
        #pragma unroll
        for (int j = 0; j < 4; j++) {
            int n = n0 + tx * 4 + j;
            C[(size_t)m * N + n] = acc[i][j] + bias[n];
        }
    }
}

// ---------------- Flash attention: per (b,h), 64-row Q tile, stream KV tiles ----------------
// Qp/Kp/Vp: [B,S,DM] with head h occupying cols [h*64, h*64+64)
// Writes combined layout ctx[b, s, h*64 + d]
#define FT 64              // tile size (both q rows and kv rows)
#define QPAD 68            // padded row for [d][r] tiles (16B aligned rows)
#define PPAD 65            // padded row for P tile

__global__ void __launch_bounds__(256) flash_attn(
    const float* __restrict__ Qp,
    const float* __restrict__ Kp,
    const float* __restrict__ Vp,
    float* __restrict__ Ctx)
{
    extern __shared__ float sm[];
    float (*Qs)[QPAD] = (float(*)[QPAD])sm;                       // [d][r]
    float (*Ks)[QPAD] = (float(*)[QPAD])(sm + FT * QPAD);         // [d][c]
    float (*Vs)[QPAD] = (float(*)[QPAD])(sm + 2 * FT * QPAD);     // [t][c]
    float (*Ps)[PPAD] = (float(*)[PPAD])(sm + 3 * FT * QPAD);     // [r][c]
    float* mrow = sm + 3 * FT * QPAD + FT * PPAD;
    float* lrow = mrow + FT;
    float* arow = lrow + FT;

    int tid = threadIdx.x;
    int tx = tid & 15;
    int ty = tid >> 4;

    int q0 = blockIdx.x * FT;
    int h  = blockIdx.y;
    int b  = blockIdx.z;

    const size_t base = (size_t)b * SQ * DM + (size_t)h * DK;
    const float* Qb = Qp + base;
    const float* Kb = Kp + base;
    const float* Vb = Vp + base;

    // load Q tile transposed: Qs[d][r]
    for (int i = tid; i < FT * (DK / 4); i += 256) {
        int r  = i >> 4;           // 0..63
        int d4 = (i & 15) * 4;     // 0..60
        float4 v = *(const float4*)(Qb + (size_t)(q0 + r) * DM + d4);
        Qs[d4 + 0][r] = v.x; Qs[d4 + 1][r] = v.y;
        Qs[d4 + 2][r] = v.z; Qs[d4 + 3][r] = v.w;
    }
    if (tid < FT) { mrow[tid] = -INFINITY; lrow[tid] = 0.0f; }

    float o[4][4] = {};
    __syncthreads();

    const float scale = 0.125f;    // 1/sqrt(64)

    for (int t0 = 0; t0 < SQ; t0 += FT) {
        // load K (transposed) and V (row-major) tiles
        for (int i = tid; i < FT * (DK / 4); i += 256) {
            int r  = i >> 4;
            int d4 = (i & 15) * 4;
            float4 kv = *(const float4*)(Kb + (size_t)(t0 + r) * DM + d4);
            Ks[d4 + 0][r] = kv.x; Ks[d4 + 1][r] = kv.y;
            Ks[d4 + 2][r] = kv.z; Ks[d4 + 3][r] = kv.w;
            float4 vv = *(const float4*)(Vb + (size_t)(t0 + r) * DM + d4);
            *(float4*)&Vs[r][d4] = vv;
        }
        __syncthreads();

        // S = (Q @ K^T) * scale, each thread computes a 4x4 block
        float sc[4][4] = {};
        #pragma unroll 8
        for (int d = 0; d < DK; d++) {
            float4 a4 = *(const float4*)&Qs[d][ty * 4];
            float4 b4 = *(const float4*)&Ks[d][tx * 4];
            float a[4] = {a4.x, a4.y, a4.z, a4.w};
            float bb[4] = {b4.x, b4.y, b4.z, b4.w};
            #pragma unroll
            for (int i = 0; i < 4; i++)
                #pragma unroll
                for (int j = 0; j < 4; j++)
                    sc[i][j] = fmaf(a[i], bb[j], sc[i][j]);
        }
        #pragma unroll
        for (int i = 0; i < 4; i++)
            #pragma unroll
            for (int j = 0; j < 4; j++)
                Ps[ty * 4 + i][tx * 4 + j] = sc[i][j] * scale;
        __syncthreads();

        // online softmax, one thread per row
        if (tid < FT) {
            int r = tid;
            float mx = mrow[r];
            #pragma unroll 8
            for (int c = 0; c < FT; c++) mx = fmaxf(mx, Ps[r][c]);
            float al = __expf(mrow[r] - mx);
            float s = 0.0f;
            #pragma unroll 8
            for (int c = 0; c < FT; c++) {
                float p = __expf(Ps[r][c] - mx);
                Ps[r][c] = p;
                s += p;
            }
            mrow[r] = mx;
            lrow[r] = lrow[r] * al + s;
            arow[r] = al;
        }
        __syncthreads();

        // rescale accumulators and O += P @ V
        float al[4];
        #pragma unroll
        for (int i = 0; i < 4; i++) al[i] = arow[ty * 4 + i];
        #pragma unroll
        for (int i = 0; i < 4; i++)
            #pragma unroll
            for (int j = 0; j < 4; j++)
                o[i][j] *= al[i];

        #pragma unroll 8
        for (int t = 0; t < FT; t++) {
            float p[4];
            #pragma unroll
            for (int i = 0; i < 4; i++) p[i] = Ps[ty * 4 + i][t];
            float4 v4 = *(const float4*)&Vs[t][tx * 4];
            float vv[4] = {v4.x, v4.y, v4.z, v4.w};
            #pragma unroll
            for (int i = 0; i < 4; i++)
                #pragma unroll
                for (int j = 0; j < 4; j++)
                    o[i][j] = fmaf(p[i], vv[j], o[i][j]);
        }
        __syncthreads();
    }

    // epilogue: normalize and write combined [B,S,H*dk]
    #pragma unroll
    for (int i = 0; i < 4; i++) {
        int r = ty * 4 + i;
        float inv_l = 1.0f / lrow[r];
        int s = q0 + r;
        float* out = Ctx + (size_t)b * SQ * DM + (size_t)s * DM + h * DK + tx * 4;
        #pragma unroll
        for (int j = 0; j < 4; j++)
            out[j] = o[i][j] * inv_l;
    }
}

// ---------------- launch ----------------
extern "C" void kernel_launch(void* const* d_in, const int* in_sizes, int n_in,
                              void* d_out, int out_size)
{
    const float* q   = (const float*)d_in[0];
    const float* k   = (const float*)d_in[1];
    const float* v   = (const float*)d_in[2];
    const float* W_q = (const float*)d_in[3];
    const float* b_q = (const float*)d_in[4];
    const float* W_k = (const float*)d_in[5];
    const float* b_k = (const float*)d_in[6];
    const float* W_v = (const float*)d_in[7];
    const float* b_v = (const float*)d_in[8];
    const float* W_o = (const float*)d_in[9];
    const float* b_o = (const float*)d_in[10];
    float* out = (float*)d_out;

    float *gq, *gk, *gv, *gctx;
    cudaGetSymbolAddress((void**)&gq, g_q);
    cudaGetSymbolAddress((void**)&gk, g_k);
    cudaGetSymbolAddress((void**)&gv, g_v);
    cudaGetSymbolAddress((void**)&gctx, g_ctx);

    dim3 gblk(DM / BN, MROWS / BM);   // (16, 64)
    gemm_nt_bias<<<gblk, 256>>>(q, W_q, b_q, gq, MROWS, DM, DM);
    gemm_nt_bias<<<gblk, 256>>>(k, W_k, b_k, gk, MROWS, DM, DM);
    gemm_nt_bias<<<gblk, 256>>>(v, W_v, b_v, gv, MROWS, DM, DM);

    int smem = (3 * FT * QPAD + FT * PPAD + 3 * FT) * (int)sizeof(float);
    cudaFuncSetAttribute(flash_attn, cudaFuncAttributeMaxDynamicSharedMemorySize, smem);
    dim3 fblk(SQ / FT, NH, BQ);       // (32, 16, 2)
    flash_attn<<<fblk, 256, smem>>>(gq, gk, gv, gctx);

    gemm_nt_bias<<<gblk, 256>>>(gctx, W_o, b_o, out, MROWS, DM, DM);
}

// round 2
// speedup vs baseline: 1.3847x; 1.3847x over previous
#include <cuda_runtime.h>
#include <cuda_bf16.h>
#include <math.h>

// Problem constants
#define BQ 2
#define SQ 2048
#define DM 1024
#define NH 16
#define DK 64
#define MROWS (BQ*SQ)   // 4096

// ---------------- scratch (allocation-free rule: __device__ globals) ----------------
__device__ float g_q[MROWS * DM];
__device__ float g_k[MROWS * DM];
__device__ float g_v[MROWS * DM];
__device__ float g_ctx[MROWS * DM];

// =====================================================================
// TF32 tensor-core GEMM: C[m,n] = sum_k A[m,k]*W[n,k] + bias[n]
// A: [M,K] row-major, W: [N,K] row-major (torch Linear => x @ W^T + b)
// CTA tile 128x128x16, 8 warps (4x2), warp tile 32x64, mma.m16n8k8.tf32
// =====================================================================
#define GPAD 20   // smem row stride in floats (bank-conflict-free fragment reads)

__device__ __forceinline__ float f2tf32(float f) {
    unsigned r;
    asm("cvt.rna.tf32.f32 %0, %1;" : "=r"(r) : "f"(f));
    return __uint_as_float(r);
}

__device__ __forceinline__ void mma_tf32(float* c, const unsigned* a, unsigned b0, unsigned b1) {
    asm volatile(
        "mma.sync.aligned.m16n8k8.row.col.f32.tf32.tf32.f32 "
        "{%0,%1,%2,%3}, {%4,%5,%6,%7}, {%8,%9}, {%0,%1,%2,%3};"
        : "+f"(c[0]), "+f"(c[1]), "+f"(c[2]), "+f"(c[3])
        : "r"(a[0]), "r"(a[1]), "r"(a[2]), "r"(a[3]), "r"(b0), "r"(b1));
}

__global__ void __launch_bounds__(256) gemm_tf32(
    const float* __restrict__ A,
    const float* __restrict__ W,
    const float* __restrict__ bias,
    float* __restrict__ C,
    int M, int N, int K)
{
    __shared__ float As[2][128 * GPAD];
    __shared__ float Ws[2][128 * GPAD];

    int tid = threadIdx.x;
    int m0 = blockIdx.y * 128;
    int n0 = blockIdx.x * 128;

    // global load mapping: 2 threads per row, 8 floats (2 float4) each
    int lrow = tid >> 1;             // 0..127
    int lcol = (tid & 1) * 8;        // 0 or 8

    const float* Ap = A + (size_t)(m0 + lrow) * K + lcol;
    const float* Wp = W + (size_t)(n0 + lrow) * K + lcol;
    float* sa = &As[0][0] + lrow * GPAD + lcol;
    float* sw = &Ws[0][0] + lrow * GPAD + lcol;
    const int stage = 128 * GPAD;

    int w    = tid >> 5;
    int lane = tid & 31;
    int wm = (w >> 1) * 32;          // warp M origin (0,32,64,96)
    int wn = (w & 1) * 64;           // warp N origin (0,64)
    int g = lane >> 2;               // 0..7
    int t = lane & 3;                // 0..3

    float acc[2][8][4] = {};

    // ---- prologue: load k-tile 0 ----
    {
        float4 a0 = *(const float4*)(Ap);
        float4 a1 = *(const float4*)(Ap + 4);
        float4 w0 = *(const float4*)(Wp);
        float4 w1 = *(const float4*)(Wp + 4);
        float4 ca0 = make_float4(f2tf32(a0.x), f2tf32(a0.y), f2tf32(a0.z), f2tf32(a0.w));
        float4 ca1 = make_float4(f2tf32(a1.x), f2tf32(a1.y), f2tf32(a1.z), f2tf32(a1.w));
        float4 cw0 = make_float4(f2tf32(w0.x), f2tf32(w0.y), f2tf32(w0.z), f2tf32(w0.w));
        float4 cw1 = make_float4(f2tf32(w1.x), f2tf32(w1.y), f2tf32(w1.z), f2tf32(w1.w));
        *(float4*)(sa)     = ca0;
        *(float4*)(sa + 4) = ca1;
        *(float4*)(sw)     = cw0;
        *(float4*)(sw + 4) = cw1;
    }
    __syncthreads();

    int buf = 0;
    for (int k0 = 0; k0 < K; k0 += 16) {
        bool has_next = (k0 + 16) < K;
        float4 na0, na1, nw0, nw1;
        if (has_next) {
            na0 = *(const float4*)(Ap + k0 + 16);
            na1 = *(const float4*)(Ap + k0 + 20);
            nw0 = *(const float4*)(Wp + k0 + 16);
            nw1 = *(const float4*)(Wp + k0 + 20);
        }

        // ---- compute on smem[buf] ----
        const float* ab = &As[buf][0];
        const float* wb = &Ws[buf][0];
        #pragma unroll
        for (int ks = 0; ks < 2; ks++) {
            unsigned af[2][4];
            #pragma unroll
            for (int mt = 0; mt < 2; mt++) {
                const float* base = ab + (wm + mt * 16 + g) * GPAD + ks * 8 + t;
                af[mt][0] = __float_as_uint(base[0]);
                af[mt][1] = __float_as_uint(base[8 * GPAD]);
                af[mt][2] = __float_as_uint(base[4]);
                af[mt][3] = __float_as_uint(base[8 * GPAD + 4]);
            }
            #pragma unroll
            for (int nt = 0; nt < 8; nt++) {
                const float* bbase = wb + (wn + nt * 8 + g) * GPAD + ks * 8 + t;
                unsigned b0 = __float_as_uint(bbase[0]);
                unsigned b1 = __float_as_uint(bbase[4]);
                #pragma unroll
                for (int mt = 0; mt < 2; mt++)
                    mma_tf32(acc[mt][nt], af[mt], b0, b1);
            }
        }

        // ---- stage next tile ----
        if (has_next) {
            float* da = sa + (buf ^ 1) * stage - buf * stage + buf * stage; // = other buffer
            // compute directly:
            float* pa = &As[buf ^ 1][0] + lrow * GPAD + lcol;
            float* pw = &Ws[buf ^ 1][0] + lrow * GPAD + lcol;
            (void)da;
            float4 ca0 = make_float4(f2tf32(na0.x), f2tf32(na0.y), f2tf32(na0.z), f2tf32(na0.w));
            float4 ca1 = make_float4(f2tf32(na1.x), f2tf32(na1.y), f2tf32(na1.z), f2tf32(na1.w));
            float4 cw0 = make_float4(f2tf32(nw0.x), f2tf32(nw0.y), f2tf32(nw0.z), f2tf32(nw0.w));
            float4 cw1 = make_float4(f2tf32(nw1.x), f2tf32(nw1.y), f2tf32(nw1.z), f2tf32(nw1.w));
            *(float4*)(pa)     = ca0;
            *(float4*)(pa + 4) = ca1;
            *(float4*)(pw)     = cw0;
            *(float4*)(pw + 4) = cw1;
            __syncthreads();
            buf ^= 1;
        }
    }

    // ---- epilogue ----
    #pragma unroll
    for (int mt = 0; mt < 2; mt++) {
        #pragma unroll
        for (int nt = 0; nt < 8; nt++) {
            int m = m0 + wm + mt * 16 + g;
            int n = n0 + wn + nt * 8 + t * 2;
            float bn0 = bias[n];
            float bn1 = bias[n + 1];
            float2 v0 = make_float2(acc[mt][nt][0] + bn0, acc[mt][nt][1] + bn1);
            float2 v1 = make_float2(acc[mt][nt][2] + bn0, acc[mt][nt][3] + bn1);
            *(float2*)&C[(size_t)m * N + n] = v0;
            *(float2*)&C[(size_t)(m + 8) * N + n] = v1;
        }
    }
}

// ---------------- Flash attention: per (b,h), 64-row Q tile, stream KV tiles ----------------
#define FT 64              // tile size (both q rows and kv rows)
#define QPAD 68            // padded row for [d][r] tiles (16B aligned rows)
#define PPAD 65            // padded row for P tile

__global__ void __launch_bounds__(256) flash_attn(
    const float* __restrict__ Qp,
    const float* __restrict__ Kp,
    const float* __restrict__ Vp,
    float* __restrict__ Ctx)
{
    extern __shared__ float sm[];
    float (*Qs)[QPAD] = (float(*)[QPAD])sm;                       // [d][r]
    float (*Ks)[QPAD] = (float(*)[QPAD])(sm + FT * QPAD);         // [d][c]
    float (*Vs)[QPAD] = (float(*)[QPAD])(sm + 2 * FT * QPAD);     // [t][c]
    float (*Ps)[PPAD] = (float(*)[PPAD])(sm + 3 * FT * QPAD);     // [r][c]
    float* mrow = sm + 3 * FT * QPAD + FT * PPAD;
    float* lrow = mrow + FT;
    float* arow = lrow + FT;

    int tid = threadIdx.x;
    int tx = tid & 15;
    int ty = tid >> 4;

    int q0 = blockIdx.x * FT;
    int h  = blockIdx.y;
    int b  = blockIdx.z;

    const size_t base = (size_t)b * SQ * DM + (size_t)h * DK;
    const float* Qb = Qp + base;
    const float* Kb = Kp + base;
    const float* Vb = Vp + base;

    // load Q tile transposed: Qs[d][r]
    for (int i = tid; i < FT * (DK / 4); i += 256) {
        int r  = i >> 4;           // 0..63
        int d4 = (i & 15) * 4;     // 0..60
        float4 v = *(const float4*)(Qb + (size_t)(q0 + r) * DM + d4);
        Qs[d4 + 0][r] = v.x; Qs[d4 + 1][r] = v.y;
        Qs[d4 + 2][r] = v.z; Qs[d4 + 3][r] = v.w;
    }
    if (tid < FT) { mrow[tid] = -INFINITY; lrow[tid] = 0.0f; }

    float o[4][4] = {};
    __syncthreads();

    const float scale = 0.125f;    // 1/sqrt(64)

    for (int t0 = 0; t0 < SQ; t0 += FT) {
        for (int i = tid; i < FT * (DK / 4); i += 256) {
            int r  = i >> 4;
            int d4 = (i & 15) * 4;
            float4 kv = *(const float4*)(Kb + (size_t)(t0 + r) * DM + d4);
            Ks[d4 + 0][r] = kv.x; Ks[d4 + 1][r] = kv.y;
            Ks[d4 + 2][r] = kv.z; Ks[d4 + 3][r] = kv.w;
            float4 vv = *(const float4*)(Vb + (size_t)(t0 + r) * DM + d4);
            *(float4*)&Vs[r][d4] = vv;
        }
        __syncthreads();

        float sc[4][4] = {};
        #pragma unroll 8
        for (int d = 0; d < DK; d++) {
            float4 a4 = *(const float4*)&Qs[d][ty * 4];
            float4 b4 = *(const float4*)&Ks[d][tx * 4];
            float a[4] = {a4.x, a4.y, a4.z, a4.w};
            float bb[4] = {b4.x, b4.y, b4.z, b4.w};
            #pragma unroll
            for (int i = 0; i < 4; i++)
                #pragma unroll
                for (int j = 0; j < 4; j++)
                    sc[i][j] = fmaf(a[i], bb[j], sc[i][j]);
        }
        #pragma unroll
        for (int i = 0; i < 4; i++)
            #pragma unroll
            for (int j = 0; j < 4; j++)
                Ps[ty * 4 + i][tx * 4 + j] = sc[i][j] * scale;
        __syncthreads();

        if (tid < FT) {
            int r = tid;
            float mx = mrow[r];
            #pragma unroll 8
            for (int c = 0; c < FT; c++) mx = fmaxf(mx, Ps[r][c]);
            float al = __expf(mrow[r] - mx);
            float s = 0.0f;
            #pragma unroll 8
            for (int c = 0; c < FT; c++) {
                float p = __expf(Ps[r][c] - mx);
                Ps[r][c] = p;
                s += p;
            }
            mrow[r] = mx;
            lrow[r] = lrow[r] * al + s;
            arow[r] = al;
        }
        __syncthreads();

        float al[4];
        #pragma unroll
        for (int i = 0; i < 4; i++) al[i] = arow[ty * 4 + i];
        #pragma unroll
        for (int i = 0; i < 4; i++)
            #pragma unroll
            for (int j = 0; j < 4; j++)
                o[i][j] *= al[i];

        #pragma unroll 8
        for (int t = 0; t < FT; t++) {
            float p[4];
            #pragma unroll
            for (int i = 0; i < 4; i++) p[i] = Ps[ty * 4 + i][t];
            float4 v4 = *(const float4*)&Vs[t][tx * 4];
            float vv[4] = {v4.x, v4.y, v4.z, v4.w};
            #pragma unroll
            for (int i = 0; i < 4; i++)
                #pragma unroll
                for (int j = 0; j < 4; j++)
                    o[i][j] = fmaf(p[i], vv[j], o[i][j]);
        }
        __syncthreads();
    }

    #pragma unroll
    for (int i = 0; i < 4; i++) {
        int r = ty * 4 + i;
        float inv_l = 1.0f / lrow[r];
        int s = q0 + r;
        float* out = Ctx + (size_t)b * SQ * DM + (size_t)s * DM + h * DK + tx * 4;
        #pragma unroll
        for (int j = 0; j < 4; j++)
            out[j] = o[i][j] * inv_l;
    }
}

// ---------------- launch ----------------
extern "C" void kernel_launch(void* const* d_in, const int* in_sizes, int n_in,
                              void* d_out, int out_size)
{
    const float* q   = (const float*)d_in[0];
    const float* k   = (const float*)d_in[1];
    const float* v   = (const float*)d_in[2];
    const float* W_q = (const float*)d_in[3];
    const float* b_q = (const float*)d_in[4];
    const float* W_k = (const float*)d_in[5];
    const float* b_k = (const float*)d_in[6];
    const float* W_v = (const float*)d_in[7];
    const float* b_v = (const float*)d_in[8];
    const float* W_o = (const float*)d_in[9];
    const float* b_o = (const float*)d_in[10];
    float* out = (float*)d_out;

    float *gq, *gk, *gv, *gctx;
    cudaGetSymbolAddress((void**)&gq, g_q);
    cudaGetSymbolAddress((void**)&gk, g_k);
    cudaGetSymbolAddress((void**)&gv, g_v);
    cudaGetSymbolAddress((void**)&gctx, g_ctx);

    dim3 gblk(DM / 128, MROWS / 128);   // (8, 32)
    gemm_tf32<<<gblk, 256>>>(q, W_q, b_q, gq, MROWS, DM, DM);
    gemm_tf32<<<gblk, 256>>>(k, W_k, b_k, gk, MROWS, DM, DM);
    gemm_tf32<<<gblk, 256>>>(v, W_v, b_v, gv, MROWS, DM, DM);

    int smem = (3 * FT * QPAD + FT * PPAD + 3 * FT) * (int)sizeof(float);
    cudaFuncSetAttribute(flash_attn, cudaFuncAttributeMaxDynamicSharedMemorySize, smem);
    dim3 fblk(SQ / FT, NH, BQ);       // (32, 16, 2)
    flash_attn<<<fblk, 256, smem>>>(gq, gk, gv, gctx);

    gemm_tf32<<<gblk, 256>>>(gctx, W_o, b_o, out, MROWS, DM, DM);
}

// round 5
// speedup vs baseline: 1.7146x; 1.2382x over previous
#include <cuda_runtime.h>
#include <cuda_bf16.h>
#include <math.h>

// Problem constants
#define BQ 2
#define SQ 2048
#define DM 1024
#define NH 16
#define DK 64
#define MROWS (BQ*SQ)   // 4096

// ---------------- scratch (allocation-free rule: __device__ globals) ----------------
__device__ float g_q[MROWS * DM];
__device__ float g_k[MROWS * DM];
__device__ float g_v[MROWS * DM];
__device__ float g_ctx[MROWS * DM];

// =====================================================================
// Common tf32 helpers
// =====================================================================
__device__ __forceinline__ float f2tf32(float f) {
    unsigned r;
    asm("cvt.rna.tf32.f32 %0, %1;" : "=r"(r) : "f"(f));
    return __uint_as_float(r);
}

__device__ __forceinline__ void mma_tf32(float* c, const unsigned* a, unsigned b0, unsigned b1) {
    asm volatile(
        "mma.sync.aligned.m16n8k8.row.col.f32.tf32.tf32.f32 "
        "{%0,%1,%2,%3}, {%4,%5,%6,%7}, {%8,%9}, {%0,%1,%2,%3};"
        : "+f"(c[0]), "+f"(c[1]), "+f"(c[2]), "+f"(c[3])
        : "r"(a[0]), "r"(a[1]), "r"(a[2]), "r"(a[3]), "r"(b0), "r"(b1));
}

__device__ __forceinline__ float ex2(float x) {
    float y;
    asm("ex2.approx.f32 %0, %1;" : "=f"(y) : "f"(x));
    return y;
}

// =====================================================================
// TF32 tensor-core GEMM: C[m,n] = sum_k A[m,k]*W[n,k] + bias[n]
// =====================================================================
#define GPAD 20

__global__ void __launch_bounds__(256) gemm_tf32(
    const float* __restrict__ A,
    const float* __restrict__ W,
    const float* __restrict__ bias,
    float* __restrict__ C,
    int M, int N, int K)
{
    __shared__ float As[2][128 * GPAD];
    __shared__ float Ws[2][128 * GPAD];

    int tid = threadIdx.x;
    int m0 = blockIdx.y * 128;
    int n0 = blockIdx.x * 128;

    int lrow = tid >> 1;
    int lcol = (tid & 1) * 8;

    const float* Ap = A + (size_t)(m0 + lrow) * K + lcol;
    const float* Wp = W + (size_t)(n0 + lrow) * K + lcol;
    float* sa = &As[0][0] + lrow * GPAD + lcol;
    float* sw = &Ws[0][0] + lrow * GPAD + lcol;

    int w    = tid >> 5;
    int lane = tid & 31;
    int wm = (w >> 1) * 32;
    int wn = (w & 1) * 64;
    int g = lane >> 2;
    int t = lane & 3;

    float acc[2][8][4] = {};

    {
        float4 a0 = *(const float4*)(Ap);
        float4 a1 = *(const float4*)(Ap + 4);
        float4 w0 = *(const float4*)(Wp);
        float4 w1 = *(const float4*)(Wp + 4);
        *(float4*)(sa)     = make_float4(f2tf32(a0.x), f2tf32(a0.y), f2tf32(a0.z), f2tf32(a0.w));
        *(float4*)(sa + 4) = make_float4(f2tf32(a1.x), f2tf32(a1.y), f2tf32(a1.z), f2tf32(a1.w));
        *(float4*)(sw)     = make_float4(f2tf32(w0.x), f2tf32(w0.y), f2tf32(w0.z), f2tf32(w0.w));
        *(float4*)(sw + 4) = make_float4(f2tf32(w1.x), f2tf32(w1.y), f2tf32(w1.z), f2tf32(w1.w));
    }
    __syncthreads();

    int buf = 0;
    for (int k0 = 0; k0 < K; k0 += 16) {
        bool has_next = (k0 + 16) < K;
        float4 na0, na1, nw0, nw1;
        if (has_next) {
            na0 = *(const float4*)(Ap + k0 + 16);
            na1 = *(const float4*)(Ap + k0 + 20);
            nw0 = *(const float4*)(Wp + k0 + 16);
            nw1 = *(const float4*)(Wp + k0 + 20);
        }

        const float* ab = &As[buf][0];
        const float* wb = &Ws[buf][0];
        #pragma unroll
        for (int ks = 0; ks < 2; ks++) {
            unsigned af[2][4];
            #pragma unroll
            for (int mt = 0; mt < 2; mt++) {
                const float* base = ab + (wm + mt * 16 + g) * GPAD + ks * 8 + t;
                af[mt][0] = __float_as_uint(base[0]);
                af[mt][1] = __float_as_uint(base[8 * GPAD]);
                af[mt][2] = __float_as_uint(base[4]);
                af[mt][3] = __float_as_uint(base[8 * GPAD + 4]);
            }
            #pragma unroll
            for (int nt = 0; nt < 8; nt++) {
                const float* bbase = wb + (wn + nt * 8 + g) * GPAD + ks * 8 + t;
                unsigned b0 = __float_as_uint(bbase[0]);
                unsigned b1 = __float_as_uint(bbase[4]);
                #pragma unroll
                for (int mt = 0; mt < 2; mt++)
                    mma_tf32(acc[mt][nt], af[mt], b0, b1);
            }
        }

        if (has_next) {
            float* pa = &As[buf ^ 1][0] + lrow * GPAD + lcol;
            float* pw = &Ws[buf ^ 1][0] + lrow * GPAD + lcol;
            *(float4*)(pa)     = make_float4(f2tf32(na0.x), f2tf32(na0.y), f2tf32(na0.z), f2tf32(na0.w));
            *(float4*)(pa + 4) = make_float4(f2tf32(na1.x), f2tf32(na1.y), f2tf32(na1.z), f2tf32(na1.w));
            *(float4*)(pw)     = make_float4(f2tf32(nw0.x), f2tf32(nw0.y), f2tf32(nw0.z), f2tf32(nw0.w));
            *(float4*)(pw + 4) = make_float4(f2tf32(nw1.x), f2tf32(nw1.y), f2tf32(nw1.z), f2tf32(nw1.w));
            __syncthreads();
            buf ^= 1;
        }
    }

    #pragma unroll
    for (int mt = 0; mt < 2; mt++) {
        #pragma unroll
        for (int nt = 0; nt < 8; nt++) {
            int m = m0 + wm + mt * 16 + g;
            int n = n0 + wn + nt * 8 + t * 2;
            float bn0 = bias[n];
            float bn1 = bias[n + 1];
            *(float2*)&C[(size_t)m * N + n]       = make_float2(acc[mt][nt][0] + bn0, acc[mt][nt][1] + bn1);
            *(float2*)&C[(size_t)(m + 8) * N + n] = make_float2(acc[mt][nt][2] + bn0, acc[mt][nt][3] + bn1);
        }
    }
}

// =====================================================================
// Tensor-core flash attention (tf32 MMA, fp32 softmax)
// CTA: 128 q-rows x one (b,h); 8 warps, each owns 16 q-rows.
// KV tiles of 64. smem pads chosen for conflict-free fragment access.
// =====================================================================
#define QT 128
#define KT 64
#define QP 68
#define KP 68
#define VP 72
#define PP 68
// smem floats: Qs 128*68 + Ks 64*68 + Vs 64*72 + Ps 128*68
#define FA_SMEM ((128*QP + 64*KP + 64*VP + 128*PP) * 4)

__global__ void __launch_bounds__(256, 2) flash_mma(
    const float* __restrict__ Qg,
    const float* __restrict__ Kg,
    const float* __restrict__ Vg,
    float* __restrict__ Ctx)
{
    extern __shared__ float sm[];
    float* Qs = sm;                       // [128][QP]
    float* Ks = Qs + 128 * QP;            // [64][KP]
    float* Vs = Ks + 64 * KP;             // [64][VP]  row-major [kv][dk]
    float* Ps = Vs + 64 * VP;             // [128][PP]

    int tid  = threadIdx.x;
    int w    = tid >> 5;
    int lane = tid & 31;
    int g = lane >> 2;       // 0..7
    int t = lane & 3;        // 0..3
    int wr = w * 16;         // warp q-row base

    int q0 = blockIdx.x * QT;
    int h  = blockIdx.y;
    int b  = blockIdx.z;

    const size_t base = (size_t)b * SQ * DM + (size_t)h * DK;
    const float* Qb = Qg + base;
    const float* Kb = Kg + base;
    const float* Vb = Vg + base;

    // ---- load Q tile once (tf32) ----
    for (int i = tid; i < QT * (DK / 4); i += 256) {
        int r  = i >> 4;
        int c4 = (i & 15) << 2;
        float4 v = *(const float4*)(Qb + (size_t)(q0 + r) * DM + c4);
        *(float4*)(Qs + r * QP + c4) =
            make_float4(f2tf32(v.x), f2tf32(v.y), f2tf32(v.z), f2tf32(v.w));
    }

    // softmax state (rows g and g+8 of this warp's band; replicated over t-quad)
    float m0 = -1e30f, m1 = -1e30f;
    float l0 = 0.0f,   l1 = 0.0f;
    float o[8][4] = {};

    const float CS = 0.125f * 1.44269504f;   // scale * log2(e)

    for (int t0 = 0; t0 < SQ; t0 += KT) {
        __syncthreads();   // previous iteration done with Ks/Vs/Ps (and Qs ready on iter 0)

        // ---- load K,V tiles (tf32) ----
        for (int i = tid; i < KT * (DK / 4); i += 256) {
            int r  = i >> 4;
            int c4 = (i & 15) << 2;
            float4 kv = *(const float4*)(Kb + (size_t)(t0 + r) * DM + c4);
            *(float4*)(Ks + r * KP + c4) =
                make_float4(f2tf32(kv.x), f2tf32(kv.y), f2tf32(kv.z), f2tf32(kv.w));
            float4 vv = *(const float4*)(Vb + (size_t)(t0 + r) * DM + c4);
            *(float4*)(Vs + r * VP + c4) =
                make_float4(f2tf32(vv.x), f2tf32(vv.y), f2tf32(vv.z), f2tf32(vv.w));
        }
        __syncthreads();

        // ---- S = Q @ K^T (warp rows wr..wr+15, cols 0..63) ----
        float sc[8][4] = {};
        #pragma unroll
        for (int ks = 0; ks < 8; ks++) {
            unsigned a[4];
            const float* ab = Qs + (wr + g) * QP + ks * 8 + t;
            a[0] = __float_as_uint(ab[0]);
            a[1] = __float_as_uint(ab[8 * QP]);
            a[2] = __float_as_uint(ab[4]);
            a[3] = __float_as_uint(ab[8 * QP + 4]);
            #pragma unroll
            for (int nb = 0; nb < 8; nb++) {
                const float* bb = Ks + (nb * 8 + g) * KP + ks * 8 + t;
                mma_tf32(sc[nb], a, __float_as_uint(bb[0]), __float_as_uint(bb[4]));
            }
        }

        // ---- online softmax on fragments (scaled to log2 domain) ----
        float mx0 = m0, mx1 = m1;
        #pragma unroll
        for (int nb = 0; nb < 8; nb++) {
            sc[nb][0] *= CS; sc[nb][1] *= CS; sc[nb][2] *= CS; sc[nb][3] *= CS;
            mx0 = fmaxf(mx0, fmaxf(sc[nb][0], sc[nb][1]));
            mx1 = fmaxf(mx1, fmaxf(sc[nb][2], sc[nb][3]));
        }
        mx0 = fmaxf(mx0, __shfl_xor_sync(0xffffffffu, mx0, 1));
        mx0 = fmaxf(mx0, __shfl_xor_sync(0xffffffffu, mx0, 2));
        mx1 = fmaxf(mx1, __shfl_xor_sync(0xffffffffu, mx1, 1));
        mx1 = fmaxf(mx1, __shfl_xor_sync(0xffffffffu, mx1, 2));

        float a0 = ex2(m0 - mx0);
        float a1 = ex2(m1 - mx1);
        m0 = mx0; m1 = mx1;

        float s0 = 0.0f, s1 = 0.0f;
        float* p0 = Ps + (wr + g) * PP;
        float* p1 = Ps + (wr + g + 8) * PP;
        #pragma unroll
        for (int nb = 0; nb < 8; nb++) {
            float e00 = ex2(sc[nb][0] - mx0);
            float e01 = ex2(sc[nb][1] - mx0);
            float e10 = ex2(sc[nb][2] - mx1);
            float e11 = ex2(sc[nb][3] - mx1);
            s0 += e00 + e01;
            s1 += e10 + e11;
            *(float2*)(p0 + nb * 8 + 2 * t) = make_float2(f2tf32(e00), f2tf32(e01));
            *(float2*)(p1 + nb * 8 + 2 * t) = make_float2(f2tf32(e10), f2tf32(e11));
        }
        s0 += __shfl_xor_sync(0xffffffffu, s0, 1);
        s0 += __shfl_xor_sync(0xffffffffu, s0, 2);
        s1 += __shfl_xor_sync(0xffffffffu, s1, 1);
        s1 += __shfl_xor_sync(0xffffffffu, s1, 2);
        l0 = l0 * a0 + s0;
        l1 = l1 * a1 + s1;

        // rescale accumulators
        #pragma unroll
        for (int nb = 0; nb < 8; nb++) {
            o[nb][0] *= a0; o[nb][1] *= a0;
            o[nb][2] *= a1; o[nb][3] *= a1;
        }

        __syncwarp();   // P rows are warp-private: warp-level fence is enough

        // ---- O += P @ V ----
        #pragma unroll
        for (int ks = 0; ks < 8; ks++) {
            unsigned a[4];
            const float* pb = Ps + (wr + g) * PP + ks * 8 + t;
            a[0] = __float_as_uint(pb[0]);
            a[1] = __float_as_uint(pb[8 * PP]);
            a[2] = __float_as_uint(pb[4]);
            a[3] = __float_as_uint(pb[8 * PP + 4]);
            #pragma unroll
            for (int nb = 0; nb < 8; nb++) {
                const float* vb = Vs + (ks * 8 + t) * VP + nb * 8 + g;
                mma_tf32(o[nb], a, __float_as_uint(vb[0]), __float_as_uint(vb[4 * VP]));
            }
        }
    }

    // ---- epilogue: normalize, write combined [B,S,H*dk] ----
    float il0 = 1.0f / l0;
    float il1 = 1.0f / l1;
    float* out0 = Ctx + (size_t)b * SQ * DM + (size_t)(q0 + wr + g) * DM + h * DK;
    float* out1 = out0 + 8 * DM;
    #pragma unroll
    for (int nb = 0; nb < 8; nb++) {
        *(float2*)(out0 + nb * 8 + 2 * t) = make_float2(o[nb][0] * il0, o[nb][1] * il0);
        *(float2*)(out1 + nb * 8 + 2 * t) = make_float2(o[nb][2] * il1, o[nb][3] * il1);
    }
}

// ---------------- launch ----------------
extern "C" void kernel_launch(void* const* d_in, const int* in_sizes, int n_in,
                              void* d_out, int out_size)
{
    const float* q   = (const float*)d_in[0];
    const float* k   = (const float*)d_in[1];
    const float* v   = (const float*)d_in[2];
    const float* W_q = (const float*)d_in[3];
    const float* b_q = (const float*)d_in[4];
    const float* W_k = (const float*)d_in[5];
    const float* b_k = (const float*)d_in[6];
    const float* W_v = (const float*)d_in[7];
    const float* b_v = (const float*)d_in[8];
    const float* W_o = (const float*)d_in[9];
    const float* b_o = (const float*)d_in[10];
    float* out = (float*)d_out;

    float *gq, *gk, *gv, *gctx;
    cudaGetSymbolAddress((void**)&gq, g_q);
    cudaGetSymbolAddress((void**)&gk, g_k);
    cudaGetSymbolAddress((void**)&gv, g_v);
    cudaGetSymbolAddress((void**)&gctx, g_ctx);

    dim3 gblk(DM / 128, MROWS / 128);   // (8, 32)
    gemm_tf32<<<gblk, 256>>>(q, W_q, b_q, gq, MROWS, DM, DM);
    gemm_tf32<<<gblk, 256>>>(k, W_k, b_k, gk, MROWS, DM, DM);
    gemm_tf32<<<gblk, 256>>>(v, W_v, b_v, gv, MROWS, DM, DM);

    cudaFuncSetAttribute(flash_mma, cudaFuncAttributeMaxDynamicSharedMemorySize, FA_SMEM);
    dim3 fblk(SQ / QT, NH, BQ);   // (16, 16, 2)
    flash_mma<<<fblk, 256, FA_SMEM>>>(gq, gk, gv, gctx);

    gemm_tf32<<<gblk, 256>>>(gctx, W_o, b_o, out, MROWS, DM, DM);
}

// round 6
// speedup vs baseline: 3.4183x; 1.9937x over previous
#include <cuda_runtime.h>
#include <cuda_bf16.h>
#include <math.h>

// Problem constants
#define BQ 2
#define SQ 2048
#define DM 1024
#define NH 16
#define DK 64
#define MROWS (BQ*SQ)   // 4096

// ---------------- scratch (allocation-free rule: __device__ globals) ----------------
__device__ float g_q[MROWS * DM];
__device__ float g_k[MROWS * DM];
__device__ float g_v[MROWS * DM];
__device__ float g_ctx[MROWS * DM];
__device__ float g_rq[MROWS * DM];
__device__ float g_rk[MROWS * DM];
__device__ float g_rv[MROWS * DM];
__device__ float g_wq[DM * DM];
__device__ float g_wk[DM * DM];
__device__ float g_wv[DM * DM];
__device__ float g_wo[DM * DM];

// =====================================================================
// helpers
// =====================================================================
__device__ __forceinline__ float f2tf32(float f) {
    unsigned r;
    asm("cvt.rna.tf32.f32 %0, %1;" : "=r"(r) : "f"(f));
    return __uint_as_float(r);
}

__device__ __forceinline__ void mma_tf32(float* c, const unsigned* a, unsigned b0, unsigned b1) {
    asm volatile(
        "mma.sync.aligned.m16n8k8.row.col.f32.tf32.tf32.f32 "
        "{%0,%1,%2,%3}, {%4,%5,%6,%7}, {%8,%9}, {%0,%1,%2,%3};"
        : "+f"(c[0]), "+f"(c[1]), "+f"(c[2]), "+f"(c[3])
        : "r"(a[0]), "r"(a[1]), "r"(a[2]), "r"(a[3]), "r"(b0), "r"(b1));
}

__device__ __forceinline__ float ex2(float x) {
    float y;
    asm("ex2.approx.f32 %0, %1;" : "=f"(y) : "f"(x));
    return y;
}

__device__ __forceinline__ void cpa16(float* s, const float* g) {
    unsigned a = (unsigned)__cvta_generic_to_shared(s);
    asm volatile("cp.async.ca.shared.global [%0], [%1], 16;" :: "r"(a), "l"(g));
}
#define CP_COMMIT() asm volatile("cp.async.commit_group;")
#define CP_WAIT(n)  asm volatile("cp.async.wait_group %0;" :: "n"(n))

// =====================================================================
// prepass: round a tensor to tf32 (RNA) into scratch
// =====================================================================
__global__ void __launch_bounds__(256) round_copy(
    const float4* __restrict__ in, float4* __restrict__ out, int n4)
{
    int i = blockIdx.x * 256 + threadIdx.x;
    if (i < n4) {
        float4 v = in[i];
        out[i] = make_float4(f2tf32(v.x), f2tf32(v.y), f2tf32(v.z), f2tf32(v.w));
    }
}

// =====================================================================
// Pipelined tf32 GEMM: C[m,n] = sum_k A[m,k]*W[n,k] + bias[n]
// A,W pre-rounded tf32. 128x128x32 tiles, 3-stage cp.async.
// blockIdx.z selects among 3 (A,W,bias,C) sets (fused QKV).
// =====================================================================
#define SAP 36    // smem row stride (floats): banks 4g+t -> conflict-free
#define GSTG 3
#define GEMM_SMEM (2 * GSTG * 128 * SAP * 4)   // 110592 B

__global__ void __launch_bounds__(256, 2) gemm3(
    const float* __restrict__ A0, const float* __restrict__ A1, const float* __restrict__ A2,
    const float* __restrict__ W0, const float* __restrict__ W1, const float* __restrict__ W2,
    const float* __restrict__ B0, const float* __restrict__ B1, const float* __restrict__ B2,
    float* __restrict__ C0, float* __restrict__ C1, float* __restrict__ C2,
    int round_out)
{
    extern __shared__ float sm[];
    float* As = sm;                         // [3][128*SAP]
    float* Ws = sm + GSTG * 128 * SAP;      // [3][128*SAP]

    int z = blockIdx.z;
    const float* A    = (z == 0) ? A0 : (z == 1) ? A1 : A2;
    const float* W    = (z == 0) ? W0 : (z == 1) ? W1 : W2;
    const float* bias = (z == 0) ? B0 : (z == 1) ? B1 : B2;
    float*       C    = (z == 0) ? C0 : (z == 1) ? C1 : C2;

    int tid = threadIdx.x;
    int m0 = blockIdx.y * 128;
    int n0 = blockIdx.x * 128;
    const float* Ab = A + (size_t)m0 * DM;
    const float* Wb = W + (size_t)n0 * DM;

    auto issue = [&](int kt, int st) {
        float* sA = As + st * 128 * SAP;
        float* sW = Ws + st * 128 * SAP;
        int k0 = kt * 32;
        #pragma unroll
        for (int i = 0; i < 4; i++) {
            int c = tid + i * 256;          // 0..1023
            int row = c >> 3;
            int col = (c & 7) << 2;
            cpa16(sA + row * SAP + col, Ab + (size_t)row * DM + k0 + col);
            cpa16(sW + row * SAP + col, Wb + (size_t)row * DM + k0 + col);
        }
        CP_COMMIT();
    };

    issue(0, 0);
    issue(1, 1);

    int w    = tid >> 5;
    int lane = tid & 31;
    int wm = (w >> 1) * 32;
    int wn = (w & 1) * 64;
    int g = lane >> 2;
    int t = lane & 3;

    float acc[2][8][4] = {};

    const int NT = DM / 32;   // 32
    int st = 0, si = 2;
    for (int kt = 0; kt < NT; kt++) {
        if (kt + 2 < NT) {
            issue(kt + 2, si);
            si = (si == 2) ? 0 : si + 1;
            CP_WAIT(2);                 // pending <=2 (kt+1, kt+2) -> stage kt done
        } else if (kt + 1 < NT) {
            CP_WAIT(1);
        } else {
            CP_WAIT(0);
        }
        __syncthreads();

        const float* ab = As + st * 128 * SAP;
        const float* wb = Ws + st * 128 * SAP;
        #pragma unroll
        for (int ks = 0; ks < 4; ks++) {
            unsigned af[2][4];
            #pragma unroll
            for (int mt = 0; mt < 2; mt++) {
                const float* bp = ab + (wm + mt * 16 + g) * SAP + ks * 8 + t;
                af[mt][0] = __float_as_uint(bp[0]);
                af[mt][1] = __float_as_uint(bp[8 * SAP]);
                af[mt][2] = __float_as_uint(bp[4]);
                af[mt][3] = __float_as_uint(bp[8 * SAP + 4]);
            }
            #pragma unroll
            for (int nt = 0; nt < 8; nt++) {
                const float* bp = wb + (wn + nt * 8 + g) * SAP + ks * 8 + t;
                unsigned b0 = __float_as_uint(bp[0]);
                unsigned b1 = __float_as_uint(bp[4]);
                mma_tf32(acc[0][nt], af[0], b0, b1);
                mma_tf32(acc[1][nt], af[1], b0, b1);
            }
        }
        __syncthreads();   // all warps done with stage st before it is refilled
        st = (st == 2) ? 0 : st + 1;
    }

    #pragma unroll
    for (int mt = 0; mt < 2; mt++) {
        #pragma unroll
        for (int nt = 0; nt < 8; nt++) {
            int m = m0 + wm + mt * 16 + g;
            int n = n0 + wn + nt * 8 + t * 2;
            float bn0 = bias[n];
            float bn1 = bias[n + 1];
            float r0 = acc[mt][nt][0] + bn0;
            float r1 = acc[mt][nt][1] + bn1;
            float r2 = acc[mt][nt][2] + bn0;
            float r3 = acc[mt][nt][3] + bn1;
            if (round_out) {
                r0 = f2tf32(r0); r1 = f2tf32(r1); r2 = f2tf32(r2); r3 = f2tf32(r3);
            }
            *(float2*)&C[(size_t)m * DM + n]       = make_float2(r0, r1);
            *(float2*)&C[(size_t)(m + 8) * DM + n] = make_float2(r2, r3);
        }
    }
}

// =====================================================================
// Tensor-core flash attention, 2-stage cp.async KV pipeline,
// register quad-shuffle P transpose (no P smem roundtrip).
// CTA: 128 q-rows x one (b,h); 8 warps x 16 q-rows. KV tiles of 64.
// Inputs pre-rounded tf32; ctx written tf32-rounded.
// =====================================================================
#define QP2 68
#define VP2 72
#define FA_SMEM ((128 * QP2 + 2 * 64 * QP2 + 2 * 64 * VP2) * 4)   // 106496 B

__global__ void __launch_bounds__(256, 2) flash_mma(
    const float* __restrict__ Qg,
    const float* __restrict__ Kg,
    const float* __restrict__ Vg,
    float* __restrict__ Ctx)
{
    extern __shared__ float sm[];
    float* Qs = sm;                        // [128][QP2]
    float* Kd = Qs + 128 * QP2;            // [2][64][QP2]
    float* Vd = Kd + 2 * 64 * QP2;         // [2][64][VP2]

    int tid  = threadIdx.x;
    int w    = tid >> 5;
    int lane = tid & 31;
    int g = lane >> 2;
    int t = lane & 3;
    int wr = w * 16;

    int q0 = blockIdx.x * 128;
    int h  = blockIdx.y;
    int b  = blockIdx.z;

    const size_t base = (size_t)b * SQ * DM + (size_t)h * DK;
    const float* Qb = Qg + base;
    const float* Kb = Kg + base;
    const float* Vb = Vg + base;

    auto issue = [&](int it, int buf) {
        const float* ksrc = Kb + (size_t)(it * 64) * DM;
        const float* vsrc = Vb + (size_t)(it * 64) * DM;
        float* kdst = Kd + buf * 64 * QP2;
        float* vdst = Vd + buf * 64 * VP2;
        #pragma unroll
        for (int i = 0; i < 4; i++) {
            int c = tid + i * 256;         // 0..1023
            int row = c >> 4;
            int col = (c & 15) << 2;
            cpa16(kdst + row * QP2 + col, ksrc + (size_t)row * DM + col);
            cpa16(vdst + row * VP2 + col, vsrc + (size_t)row * DM + col);
        }
        CP_COMMIT();
    };

    issue(0, 0);

    // Q tile (already tf32-rounded): plain copy
    for (int i = tid; i < 128 * 16; i += 256) {
        int r  = i >> 4;
        int c4 = (i & 15) << 2;
        *(float4*)(Qs + r * QP2 + c4) = *(const float4*)(Qb + (size_t)(q0 + r) * DM + c4);
    }

    float m0 = -1e30f, m1 = -1e30f;
    float l0 = 0.0f,   l1 = 0.0f;
    float o[8][4] = {};
    const float CS = 0.125f * 1.44269504f;   // scale * log2(e)

    const int NT = SQ / 64;   // 32
    int src0 = (lane & ~3) | (t >> 1);
    bool odd = t & 1;

    for (int it = 0; it < NT; it++) {
        int buf = it & 1;
        if (it + 1 < NT) { issue(it + 1, buf ^ 1); CP_WAIT(1); }
        else             { CP_WAIT(0); }
        __syncthreads();

        const float* Ks = Kd + buf * 64 * QP2;
        const float* Vs = Vd + buf * 64 * VP2;

        // ---- S = Q @ K^T ----
        float sc[8][4] = {};
        #pragma unroll
        for (int ks = 0; ks < 8; ks++) {
            unsigned a[4];
            const float* ab = Qs + (wr + g) * QP2 + ks * 8 + t;
            a[0] = __float_as_uint(ab[0]);
            a[1] = __float_as_uint(ab[8 * QP2]);
            a[2] = __float_as_uint(ab[4]);
            a[3] = __float_as_uint(ab[8 * QP2 + 4]);
            #pragma unroll
            for (int nb = 0; nb < 8; nb++) {
                const float* bb = Ks + (nb * 8 + g) * QP2 + ks * 8 + t;
                mma_tf32(sc[nb], a, __float_as_uint(bb[0]), __float_as_uint(bb[4]));
            }
        }

        // ---- online softmax (log2 domain) ----
        float mx0 = m0, mx1 = m1;
        #pragma unroll
        for (int nb = 0; nb < 8; nb++) {
            sc[nb][0] *= CS; sc[nb][1] *= CS; sc[nb][2] *= CS; sc[nb][3] *= CS;
            mx0 = fmaxf(mx0, fmaxf(sc[nb][0], sc[nb][1]));
            mx1 = fmaxf(mx1, fmaxf(sc[nb][2], sc[nb][3]));
        }
        mx0 = fmaxf(mx0, __shfl_xor_sync(0xffffffffu, mx0, 1));
        mx0 = fmaxf(mx0, __shfl_xor_sync(0xffffffffu, mx0, 2));
        mx1 = fmaxf(mx1, __shfl_xor_sync(0xffffffffu, mx1, 1));
        mx1 = fmaxf(mx1, __shfl_xor_sync(0xffffffffu, mx1, 2));

        float a0 = ex2(m0 - mx0);
        float a1 = ex2(m1 - mx1);
        m0 = mx0; m1 = mx1;

        float s0 = 0.0f, s1 = 0.0f;
        #pragma unroll
        for (int nb = 0; nb < 8; nb++) {
            float e00 = ex2(sc[nb][0] - mx0);
            float e01 = ex2(sc[nb][1] - mx0);
            float e10 = ex2(sc[nb][2] - mx1);
            float e11 = ex2(sc[nb][3] - mx1);
            s0 += e00 + e01;
            s1 += e10 + e11;
            sc[nb][0] = f2tf32(e00);
            sc[nb][1] = f2tf32(e01);
            sc[nb][2] = f2tf32(e10);
            sc[nb][3] = f2tf32(e11);
        }
        s0 += __shfl_xor_sync(0xffffffffu, s0, 1);
        s0 += __shfl_xor_sync(0xffffffffu, s0, 2);
        s1 += __shfl_xor_sync(0xffffffffu, s1, 1);
        s1 += __shfl_xor_sync(0xffffffffu, s1, 2);
        l0 = l0 * a0 + s0;
        l1 = l1 * a1 + s1;

        #pragma unroll
        for (int nb = 0; nb < 8; nb++) {
            o[nb][0] *= a0; o[nb][1] *= a0;
            o[nb][2] *= a1; o[nb][3] *= a1;
        }

        // ---- O += P @ V : quad-shuffle transpose of P (C-layout -> A-frag) ----
        #pragma unroll
        for (int ks = 0; ks < 8; ks++) {
            float v00 = __shfl_sync(0xffffffffu, sc[ks][0], src0);
            float v01 = __shfl_sync(0xffffffffu, sc[ks][1], src0);
            float v10 = __shfl_sync(0xffffffffu, sc[ks][2], src0);
            float v11 = __shfl_sync(0xffffffffu, sc[ks][3], src0);
            float w00 = __shfl_sync(0xffffffffu, sc[ks][0], src0 + 2);
            float w01 = __shfl_sync(0xffffffffu, sc[ks][1], src0 + 2);
            float w10 = __shfl_sync(0xffffffffu, sc[ks][2], src0 + 2);
            float w11 = __shfl_sync(0xffffffffu, sc[ks][3], src0 + 2);
            unsigned a[4];
            a[0] = __float_as_uint(odd ? v01 : v00);   // row g,   col t
            a[1] = __float_as_uint(odd ? v11 : v10);   // row g+8, col t
            a[2] = __float_as_uint(odd ? w01 : w00);   // row g,   col t+4
            a[3] = __float_as_uint(odd ? w11 : w10);   // row g+8, col t+4
            #pragma unroll
            for (int nb = 0; nb < 8; nb++) {
                const float* vb = Vs + (ks * 8 + t) * VP2 + nb * 8 + g;
                mma_tf32(o[nb], a, __float_as_uint(vb[0]), __float_as_uint(vb[4 * VP2]));
            }
        }
        __syncthreads();   // all reads of this KV buffer done before refill
    }

    // ---- epilogue: normalize, round to tf32, write combined [B,S,H*dk] ----
    float il0 = 1.0f / l0;
    float il1 = 1.0f / l1;
    float* out0 = Ctx + (size_t)b * SQ * DM + (size_t)(q0 + wr + g) * DM + h * DK;
    float* out1 = out0 + 8 * DM;
    #pragma unroll
    for (int nb = 0; nb < 8; nb++) {
        *(float2*)(out0 + nb * 8 + 2 * t) =
            make_float2(f2tf32(o[nb][0] * il0), f2tf32(o[nb][1] * il0));
        *(float2*)(out1 + nb * 8 + 2 * t) =
            make_float2(f2tf32(o[nb][2] * il1), f2tf32(o[nb][3] * il1));
    }
}

// ---------------- launch ----------------
extern "C" void kernel_launch(void* const* d_in, const int* in_sizes, int n_in,
                              void* d_out, int out_size)
{
    const float* q   = (const float*)d_in[0];
    const float* k   = (const float*)d_in[1];
    const float* v   = (const float*)d_in[2];
    const float* W_q = (const float*)d_in[3];
    const float* b_q = (const float*)d_in[4];
    const float* W_k = (const float*)d_in[5];
    const float* b_k = (const float*)d_in[6];
    const float* W_v = (const float*)d_in[7];
    const float* b_v = (const float*)d_in[8];
    const float* W_o = (const float*)d_in[9];
    const float* b_o = (const float*)d_in[10];
    float* out = (float*)d_out;

    float *gq, *gk, *gv, *gctx, *grq, *grk, *grv, *gwq, *gwk, *gwv, *gwo;
    cudaGetSymbolAddress((void**)&gq,  g_q);
    cudaGetSymbolAddress((void**)&gk,  g_k);
    cudaGetSymbolAddress((void**)&gv,  g_v);
    cudaGetSymbolAddress((void**)&gctx, g_ctx);
    cudaGetSymbolAddress((void**)&grq, g_rq);
    cudaGetSymbolAddress((void**)&grk, g_rk);
    cudaGetSymbolAddress((void**)&grv, g_rv);
    cudaGetSymbolAddress((void**)&gwq, g_wq);
    cudaGetSymbolAddress((void**)&gwk, g_wk);
    cudaGetSymbolAddress((void**)&gwv, g_wv);
    cudaGetSymbolAddress((void**)&gwo, g_wo);

    // prepass: round activations + weights to tf32
    const int NA4 = MROWS * DM / 4;   // 1048576
    const int NW4 = DM * DM / 4;      // 262144
    round_copy<<<NA4 / 256, 256>>>((const float4*)q, (float4*)grq, NA4);
    round_copy<<<NA4 / 256, 256>>>((const float4*)k, (float4*)grk, NA4);
    round_copy<<<NA4 / 256, 256>>>((const float4*)v, (float4*)grv, NA4);
    round_copy<<<NW4 / 256, 256>>>((const float4*)W_q, (float4*)gwq, NW4);
    round_copy<<<NW4 / 256, 256>>>((const float4*)W_k, (float4*)gwk, NW4);
    round_copy<<<NW4 / 256, 256>>>((const float4*)W_v, (float4*)gwv, NW4);
    round_copy<<<NW4 / 256, 256>>>((const float4*)W_o, (float4*)gwo, NW4);

    cudaFuncSetAttribute(gemm3, cudaFuncAttributeMaxDynamicSharedMemorySize, GEMM_SMEM);
    cudaFuncSetAttribute(flash_mma, cudaFuncAttributeMaxDynamicSharedMemorySize, FA_SMEM);

    // fused Q/K/V projections (rounded tf32 outputs)
    gemm3<<<dim3(DM / 128, MROWS / 128, 3), 256, GEMM_SMEM>>>(
        grq, grk, grv, gwq, gwk, gwv, b_q, b_k, b_v, gq, gk, gv, 1);

    // flash attention (writes tf32-rounded ctx)
    flash_mma<<<dim3(SQ / 128, NH, BQ), 256, FA_SMEM>>>(gq, gk, gv, gctx);

    // output projection (fp32 output)
    gemm3<<<dim3(DM / 128, MROWS / 128, 1), 256, GEMM_SMEM>>>(
        gctx, gctx, gctx, gwo, gwo, gwo, b_o, b_o, b_o, out, out, out, 0);
}